// round 11
// baseline (speedup 1.0000x reference)
#include <cuda_runtime.h>
#include <cuda_fp16.h>

#define N_NODES  10000
#define N_EDGES  640000
#define N_GRAPHS 64
#define F        128

// -------- device symbols: ONLY dereferenced inside kernels, never passed as args --------
__device__ int    g_deg_out[N_NODES];          // zeroed at load + by k_final each run
__device__ int    g_deg_in [N_NODES];
__device__ float  g_norm_src[N_NODES];
__device__ float  g_norm_dst[N_NODES];
__device__ int    g_row_ptr[N_NODES + 1];
__device__ int    g_cursor [N_NODES];
__device__ int    g_csr    [N_EDGES];
__device__ __half g_xh     [N_NODES * F];      // in_feat * norm_src   (fp16)
__device__ __half g_h1h    [N_NODES * F];      // relu(layer1) * norm_src (fp16)
__device__ __half g_w1h    [F * F];            // W1 in fp16
__device__ __half g_w2h    [F * F];            // W2 in fp16
__device__ float  g_gsum   [N_GRAPHS];
__device__ float  g_ginv   [N_GRAPHS];

#define TB 256

// ---------------- [0] degrees (4 edges per thread, int4 loads) ----------------
__global__ void k_degree(const int* __restrict__ src, const int* __restrict__ dst) {
    int i = blockIdx.x * blockDim.x + threadIdx.x;
    if (i < N_EDGES / 4) {
        int4 s = ((const int4*)src)[i];
        int4 d = ((const int4*)dst)[i];
        atomicAdd(&g_deg_out[s.x], 1);
        atomicAdd(&g_deg_out[s.y], 1);
        atomicAdd(&g_deg_out[s.z], 1);
        atomicAdd(&g_deg_out[s.w], 1);
        atomicAdd(&g_deg_in[d.x], 1);
        atomicAdd(&g_deg_in[d.y], 1);
        atomicAdd(&g_deg_in[d.z], 1);
        atomicAdd(&g_deg_in[d.w], 1);
    }
}

// ---------------- [1] prep: norms + graph counts + shuffle-scan + cursors (1 block) --------
__global__ void k_prep(const int* __restrict__ gids) {
    const int T = 1024, C = 10;                // 1024*10 = 10240 >= N_NODES
    __shared__ int wsum[32];
    __shared__ int cnt[N_GRAPHS];
    int t    = threadIdx.x;
    int wid  = t >> 5;
    int lane = t & 31;
    if (t < N_GRAPHS) cnt[t] = 0;
    __syncthreads();

    for (int n = t; n < N_NODES; n += T) {
        g_norm_src[n] = rsqrtf((float)max(g_deg_out[n], 1));
        g_norm_dst[n] = rsqrtf((float)max(g_deg_in [n], 1));
        atomicAdd(&cnt[gids[n]], 1);
    }

    int base = t * C;
    int local = 0;
    #pragma unroll
    for (int i = 0; i < C; i++) {
        int idx = base + i;
        if (idx < N_NODES) local += g_deg_in[idx];
    }
    int v = local;
    #pragma unroll
    for (int off = 1; off < 32; off <<= 1) {
        int u = __shfl_up_sync(0xffffffffu, v, off);
        if (lane >= off) v += u;
    }
    if (lane == 31) wsum[wid] = v;
    __syncthreads();
    if (wid == 0) {
        int u = wsum[lane];
        #pragma unroll
        for (int off = 1; off < 32; off <<= 1) {
            int p = __shfl_up_sync(0xffffffffu, u, off);
            if (lane >= off) u += p;
        }
        wsum[lane] = u;
    }
    __syncthreads();
    int run = v - local + (wid > 0 ? wsum[wid - 1] : 0);
    #pragma unroll
    for (int i = 0; i < C; i++) {
        int idx = base + i;
        if (idx < N_NODES) {
            g_row_ptr[idx] = run;
            g_cursor [idx] = run;
            run += g_deg_in[idx];
        }
    }
    if (t == T - 1) g_row_ptr[N_NODES] = run;

    if (t < N_GRAPHS) {
        g_gsum[t] = 0.f;
        g_ginv[t] = 1.f / fmaxf((float)cnt[t], 1.f);
    }
}

// ------- [2] scatter edges into CSR (int4) + prescale X to fp16 + convert W to fp16 -------
#define EDGE4_BLOCKS ((N_EDGES / 4 + TB - 1) / TB)
#define XS_BLOCKS    ((N_NODES * (F / 4) + TB - 1) / TB)
#define W_BLOCKS     ((F * F / 4 + TB - 1) / TB)

__global__ void k_scatter_scale(const int* __restrict__ src,
                                const int* __restrict__ dst,
                                const float* __restrict__ X,
                                const float* __restrict__ W1,
                                const float* __restrict__ W2) {
    int b = blockIdx.x;
    if (b < EDGE4_BLOCKS) {
        int i = b * TB + threadIdx.x;
        if (i < N_EDGES / 4) {
            int4 s = ((const int4*)src)[i];
            int4 d = ((const int4*)dst)[i];
            g_csr[atomicAdd(&g_cursor[d.x], 1)] = s.x;
            g_csr[atomicAdd(&g_cursor[d.y], 1)] = s.y;
            g_csr[atomicAdd(&g_cursor[d.z], 1)] = s.z;
            g_csr[atomicAdd(&g_cursor[d.w], 1)] = s.w;
        }
    } else if (b < EDGE4_BLOCKS + XS_BLOCKS) {
        int idx = (b - EDGE4_BLOCKS) * TB + threadIdx.x;
        if (idx < N_NODES * (F / 4)) {
            float s = g_norm_src[idx >> 5];
            float4 v = ((const float4*)X)[idx];
            __half2 h0 = __floats2half2_rn(v.x * s, v.y * s);
            __half2 h1 = __floats2half2_rn(v.z * s, v.w * s);
            uint2 o;
            o.x = *(unsigned*)&h0;
            o.y = *(unsigned*)&h1;
            ((uint2*)g_xh)[idx] = o;
        }
    } else {
        int idx = (b - EDGE4_BLOCKS - XS_BLOCKS) * TB + threadIdx.x;
        if (idx < 2 * (F * F / 4)) {
            int m = idx >= F * F / 4;
            int i = m ? idx - F * F / 4 : idx;
            float4 v = ((const float4*)(m ? W2 : W1))[i];
            __half2 h0 = __floats2half2_rn(v.x, v.y);
            __half2 h1 = __floats2half2_rn(v.z, v.w);
            uint2 o;
            o.x = *(unsigned*)&h0;
            o.y = *(unsigned*)&h1;
            ((uint2*)(m ? g_w2h : g_w1h))[i] = o;
        }
    }
}

// ------- [3]/[4] fused layer: warp-per-node, fp16 gather (16-deep) + fp16-W fp32-acc GEMM ---
#define WARPS 8   // nodes per block = 8

template <int LAYER>    // 1: read g_xh/g_w1h, write g_h1h; 2: read g_h1h/g_w2h, fused pool
__global__ __launch_bounds__(256) void k_layer(const float* __restrict__ b,
                                               const float* __restrict__ Wd,
                                               const int*  __restrict__ gids) {
    __shared__ float rowbuf[WARPS][F];
    int w    = threadIdx.x >> 5;
    int lane = threadIdx.x & 31;
    int n    = blockIdx.x * WARPS + w;
    if (n >= N_NODES) return;

    const uint2* X  = (const uint2*)(LAYER == 1 ? (const __half*)g_xh
                                                : (const __half*)g_h1h);
    const uint2* Wh = (const uint2*)(LAYER == 1 ? (const __half*)g_w1h
                                                : (const __half*)g_w2h);

    int beg = g_row_ptr[n], end = g_row_ptr[n + 1];
    float ax = 0.f, ay = 0.f, az = 0.f, aw = 0.f;
    int e = beg;
    #define ACC(v) { \
        float2 f0 = __half22float2(*(__half2*)&(v).x); \
        float2 f1 = __half22float2(*(__half2*)&(v).y); \
        ax += f0.x; ay += f0.y; az += f1.x; aw += f1.y; }
    for (; e + 16 <= end; e += 16) {               // 32 loads in flight
        uint2 v[16];
        #pragma unroll
        for (int q = 0; q < 16; q++) v[q] = X[g_csr[e + q] * 32 + lane];
        #pragma unroll
        for (int q = 0; q < 16; q++) ACC(v[q])
    }
    for (; e + 4 <= end; e += 4) {
        uint2 v0 = X[g_csr[e+0] * 32 + lane];
        uint2 v1 = X[g_csr[e+1] * 32 + lane];
        uint2 v2 = X[g_csr[e+2] * 32 + lane];
        uint2 v3 = X[g_csr[e+3] * 32 + lane];
        ACC(v0) ACC(v1) ACC(v2) ACC(v3)
    }
    for (; e < end; e++) {
        uint2 v = X[g_csr[e] * 32 + lane];
        ACC(v)
    }
    #undef ACC

    float nd = g_norm_dst[n];
    ((float4*)rowbuf[w])[lane] = make_float4(ax * nd, ay * nd, az * nd, aw * nd);
    __syncwarp();

    // GEMM: o[c] = sum_k row[k] * W[k][c] + b[c]   (fp16 W, fp32 acc)
    float4 bv = ((const float4*)b)[lane];
    float ox = bv.x, oy = bv.y, oz = bv.z, ow = bv.w;
    const float* r = rowbuf[w];
    #pragma unroll 8
    for (int k = 0; k < F; k++) {
        uint2 wv = Wh[k * 32 + lane];              // LDG.64, L1-resident
        float2 w01 = __half22float2(*(__half2*)&wv.x);
        float2 w23 = __half22float2(*(__half2*)&wv.y);
        float a = r[k];                            // LDS broadcast
        ox += a * w01.x; oy += a * w01.y; oz += a * w23.x; ow += a * w23.y;
    }
    ox = fmaxf(ox, 0.f); oy = fmaxf(oy, 0.f);
    oz = fmaxf(oz, 0.f); ow = fmaxf(ow, 0.f);

    if (LAYER == 1) {
        float ns = g_norm_src[n];
        __half2 h0 = __floats2half2_rn(ox * ns, oy * ns);
        __half2 h1 = __floats2half2_rn(oz * ns, ow * ns);
        uint2 o;
        o.x = *(unsigned*)&h0;
        o.y = *(unsigned*)&h1;
        ((uint2*)g_h1h)[n * 32 + lane] = o;
    } else {
        float4 wd = ((const float4*)Wd)[lane];
        float z = ox * wd.x + oy * wd.y + oz * wd.z + ow * wd.w;
        #pragma unroll
        for (int off = 16; off > 0; off >>= 1)
            z += __shfl_xor_sync(0xffffffffu, z, off);
        if (lane == 0) atomicAdd(&g_gsum[gids[n]], z);
    }
}

// ---------------- [5] readout + re-zero degree arrays for next run ----------------
__global__ void k_final(const float* __restrict__ bd, float* __restrict__ out) {
    int i = blockIdx.x * blockDim.x + threadIdx.x;
    if (i < N_NODES) { g_deg_out[i] = 0; g_deg_in[i] = 0; }
    if (i < N_GRAPHS) out[i] = g_gsum[i] * g_ginv[i] + bd[0];
}

// ---------------- launch ----------------
extern "C" void kernel_launch(void* const* d_in, const int* in_sizes, int n_in,
                              void* d_out, int out_size) {
    const float* in_feat = (const float*)d_in[0];
    const int*   src     = (const int*)  d_in[1];
    const int*   dst     = (const int*)  d_in[2];
    const int*   gids    = (const int*)  d_in[3];
    const float* W1      = (const float*)d_in[4];
    const float* b1      = (const float*)d_in[5];
    const float* W2      = (const float*)d_in[6];
    const float* b2      = (const float*)d_in[7];
    const float* Wd      = (const float*)d_in[8];
    const float* bd      = (const float*)d_in[9];
    float* out = (float*)d_out;

    int layerBlocks = (N_NODES + WARPS - 1) / WARPS;   // 1250
    int finalBlocks = (N_NODES + TB - 1) / TB;
    int ssBlocks    = EDGE4_BLOCKS + XS_BLOCKS + 2 * W_BLOCKS;

    k_degree        <<<EDGE4_BLOCKS, TB>>>(src, dst);                     // 0
    k_prep          <<<1, 1024>>>(gids);                                  // 1
    k_scatter_scale <<<ssBlocks, TB>>>(src, dst, in_feat, W1, W2);        // 2
    k_layer<1>      <<<layerBlocks, TB>>>(b1, nullptr, nullptr);          // 3  (ncu slot)
    k_layer<2>      <<<layerBlocks, TB>>>(b2, Wd, gids);                  // 4
    k_final         <<<finalBlocks, TB>>>(bd, out);                       // 5
}

// round 12
// speedup vs baseline: 1.0431x; 1.0431x over previous
#include <cuda_runtime.h>
#include <cuda_fp16.h>
#include <mma.h>

using namespace nvcuda;

#define N_NODES  10000
#define N_EDGES  640000
#define N_GRAPHS 64
#define F        128

// -------- device symbols: ONLY dereferenced inside kernels, never passed as args --------
__device__ int    g_deg_out[N_NODES];          // zeroed at load + by k_final each run
__device__ int    g_deg_in [N_NODES];
__device__ int    g_row_ptr[N_NODES + 1];
__device__ int    g_cursor [N_NODES];
__device__ int    g_csr    [N_EDGES];
__device__ __half g_xh     [N_NODES * F];      // in_feat * norm_src            (fp16)
__device__ __half g_h1s    [N_NODES * F];      // relu(layer1) * norm_src       (fp16)
__device__ __half g_zh     [N_NODES * F];      // Z = input @ W  (per layer)    (fp16)
__device__ __half g_w1h    [F * F];            // W1 fp16
__device__ __half g_w2h    [F * F];            // W2 fp16
__device__ float  g_gsum   [N_GRAPHS];
__device__ float  g_ginv   [N_GRAPHS];

#define TB 256

// ---------------- [0] degrees (4 edges per thread, int4 loads) ----------------
__global__ void k_degree(const int* __restrict__ src, const int* __restrict__ dst) {
    int i = blockIdx.x * blockDim.x + threadIdx.x;
    if (i < N_EDGES / 4) {
        int4 s = ((const int4*)src)[i];
        int4 d = ((const int4*)dst)[i];
        atomicAdd(&g_deg_out[s.x], 1);
        atomicAdd(&g_deg_out[s.y], 1);
        atomicAdd(&g_deg_out[s.z], 1);
        atomicAdd(&g_deg_out[s.w], 1);
        atomicAdd(&g_deg_in[d.x], 1);
        atomicAdd(&g_deg_in[d.y], 1);
        atomicAdd(&g_deg_in[d.z], 1);
        atomicAdd(&g_deg_in[d.w], 1);
    }
}

// ------ [1] prep: shuffle-scan of in-degrees + cursors + per-graph counts (binary search) ---
__global__ void k_prep(const int* __restrict__ gids) {
    const int T = 1024, C = 10;                // 1024*10 = 10240 >= N_NODES
    __shared__ int wsum[32];
    int t    = threadIdx.x;
    int wid  = t >> 5;
    int lane = t & 31;

    int base = t * C;
    int local = 0;
    #pragma unroll
    for (int i = 0; i < C; i++) {
        int idx = base + i;
        if (idx < N_NODES) local += g_deg_in[idx];
    }
    int v = local;
    #pragma unroll
    for (int off = 1; off < 32; off <<= 1) {
        int u = __shfl_up_sync(0xffffffffu, v, off);
        if (lane >= off) v += u;
    }
    if (lane == 31) wsum[wid] = v;
    __syncthreads();
    if (wid == 0) {
        int u = wsum[lane];
        #pragma unroll
        for (int off = 1; off < 32; off <<= 1) {
            int p = __shfl_up_sync(0xffffffffu, u, off);
            if (lane >= off) u += p;
        }
        wsum[lane] = u;
    }
    __syncthreads();
    int run = v - local + (wid > 0 ? wsum[wid - 1] : 0);
    #pragma unroll
    for (int i = 0; i < C; i++) {
        int idx = base + i;
        if (idx < N_NODES) {
            g_row_ptr[idx] = run;
            g_cursor [idx] = run;
            run += g_deg_in[idx];
        }
    }
    if (t == T - 1) g_row_ptr[N_NODES] = run;

    // per-graph counts: graph_ids is sorted -> binary search boundaries
    if (t < N_GRAPHS) {
        int lo = 0, hi = N_NODES;              // lower_bound(t)
        while (lo < hi) { int m = (lo + hi) >> 1; if (gids[m] < t) lo = m + 1; else hi = m; }
        int b0 = lo;
        lo = b0; hi = N_NODES;                 // lower_bound(t+1)
        while (lo < hi) { int m = (lo + hi) >> 1; if (gids[m] < t + 1) lo = m + 1; else hi = m; }
        int c = lo - b0;
        g_gsum[t] = 0.f;
        g_ginv[t] = 1.f / fmaxf((float)c, 1.f);
    }
}

// ------- [2] scatter edges into CSR (int4) + prescale X to fp16 + convert W to fp16 -------
#define EDGE4_BLOCKS ((N_EDGES / 4 + TB - 1) / TB)
#define XS_BLOCKS    ((N_NODES * (F / 4) + TB - 1) / TB)
#define W_BLOCKS     ((F * F / 4 + TB - 1) / TB)

__global__ void k_scatter_scale(const int* __restrict__ src,
                                const int* __restrict__ dst,
                                const float* __restrict__ X,
                                const float* __restrict__ W1,
                                const float* __restrict__ W2) {
    int b = blockIdx.x;
    if (b < EDGE4_BLOCKS) {
        int i = b * TB + threadIdx.x;
        if (i < N_EDGES / 4) {
            int4 s = ((const int4*)src)[i];
            int4 d = ((const int4*)dst)[i];
            g_csr[atomicAdd(&g_cursor[d.x], 1)] = s.x;
            g_csr[atomicAdd(&g_cursor[d.y], 1)] = s.y;
            g_csr[atomicAdd(&g_cursor[d.z], 1)] = s.z;
            g_csr[atomicAdd(&g_cursor[d.w], 1)] = s.w;
        }
    } else if (b < EDGE4_BLOCKS + XS_BLOCKS) {
        int idx = (b - EDGE4_BLOCKS) * TB + threadIdx.x;
        if (idx < N_NODES * (F / 4)) {
            float s = rsqrtf((float)max(g_deg_out[idx >> 5], 1));   // norm_src inline
            float4 v = ((const float4*)X)[idx];
            __half2 h0 = __floats2half2_rn(v.x * s, v.y * s);
            __half2 h1 = __floats2half2_rn(v.z * s, v.w * s);
            uint2 o;
            o.x = *(unsigned*)&h0;
            o.y = *(unsigned*)&h1;
            ((uint2*)g_xh)[idx] = o;
        }
    } else {
        int idx = (b - EDGE4_BLOCKS - XS_BLOCKS) * TB + threadIdx.x;
        if (idx < 2 * (F * F / 4)) {
            int m = idx >= F * F / 4;
            int i = m ? idx - F * F / 4 : idx;
            float4 v = ((const float4*)(m ? W2 : W1))[i];
            __half2 h0 = __floats2half2_rn(v.x, v.y);
            __half2 h1 = __floats2half2_rn(v.z, v.w);
            uint2 o;
            o.x = *(unsigned*)&h0;
            o.y = *(unsigned*)&h1;
            ((uint2*)(m ? g_w2h : g_w1h))[i] = o;
        }
    }
}

// ---------------- [3]/[5] dense GEMM via wmma: Z = A @ W  (fp16 x fp16 -> fp16) -----------
// block = 256 threads = 8 warps; block handles 16 rows x 128 cols; warp w -> col tile w*16.
template <int LAYER>    // 1: A=g_xh, W=g_w1h; 2: A=g_h1s, W=g_w2h
__global__ __launch_bounds__(256) void k_gemm() {
    const __half* A = LAYER == 1 ? g_xh  : g_h1s;
    const __half* W = LAYER == 1 ? g_w1h : g_w2h;
    int warp = threadIdx.x >> 5;
    int row0 = blockIdx.x * 16;
    int col0 = warp * 16;

    wmma::fragment<wmma::matrix_a, 16, 16, 16, half, wmma::row_major> af;
    wmma::fragment<wmma::matrix_b, 16, 16, 16, half, wmma::row_major> bf;
    wmma::fragment<wmma::accumulator, 16, 16, 16, half> cf;
    wmma::fill_fragment(cf, __float2half(0.f));

    #pragma unroll
    for (int k = 0; k < F / 16; k++) {
        wmma::load_matrix_sync(af, (const half*)A + row0 * F + k * 16, F);
        wmma::load_matrix_sync(bf, (const half*)W + (k * 16) * F + col0, F);
        wmma::mma_sync(cf, af, bf, cf);
    }
    wmma::store_matrix_sync((half*)g_zh + row0 * F + col0, cf, F, wmma::mem_row_major);
}

// ---------------- [4]/[6] aggregate: warp-per-node gather of Z + epilogue ----------------
template <int LAYER>    // 1: write h1s = relu(nd*acc+b)*ns; 2: pool relu(nd*acc+b).Wd
__global__ __launch_bounds__(256) void k_agg(const float* __restrict__ b,
                                             const float* __restrict__ Wd,
                                             const int*  __restrict__ gids) {
    const int WARPS = 8;
    int w    = threadIdx.x >> 5;
    int lane = threadIdx.x & 31;
    int n    = blockIdx.x * WARPS + w;
    if (n >= N_NODES) return;

    const uint2* Z = (const uint2*)g_zh;

    int beg = g_row_ptr[n], end = g_row_ptr[n + 1];
    float ax = 0.f, ay = 0.f, az = 0.f, aw = 0.f;
    int e = beg;
    #define ACC(v) { \
        float2 f0 = __half22float2(*(__half2*)&(v).x); \
        float2 f1 = __half22float2(*(__half2*)&(v).y); \
        ax += f0.x; ay += f0.y; az += f1.x; aw += f1.y; }
    for (; e + 16 <= end; e += 16) {               // 32 loads in flight
        uint2 v[16];
        #pragma unroll
        for (int q = 0; q < 16; q++) v[q] = Z[g_csr[e + q] * 32 + lane];
        #pragma unroll
        for (int q = 0; q < 16; q++) ACC(v[q])
    }
    for (; e + 4 <= end; e += 4) {
        uint2 v0 = Z[g_csr[e+0] * 32 + lane];
        uint2 v1 = Z[g_csr[e+1] * 32 + lane];
        uint2 v2 = Z[g_csr[e+2] * 32 + lane];
        uint2 v3 = Z[g_csr[e+3] * 32 + lane];
        ACC(v0) ACC(v1) ACC(v2) ACC(v3)
    }
    for (; e < end; e++) {
        uint2 v = Z[g_csr[e] * 32 + lane];
        ACC(v)
    }
    #undef ACC

    float nd = rsqrtf((float)max(g_deg_in[n], 1));   // norm_dst inline
    float4 bv = ((const float4*)b)[lane];
    float ox = fmaxf(ax * nd + bv.x, 0.f);
    float oy = fmaxf(ay * nd + bv.y, 0.f);
    float oz = fmaxf(az * nd + bv.z, 0.f);
    float ow = fmaxf(aw * nd + bv.w, 0.f);

    if (LAYER == 1) {
        float ns = rsqrtf((float)max(g_deg_out[n], 1));  // prescale for layer-2 GEMM
        __half2 h0 = __floats2half2_rn(ox * ns, oy * ns);
        __half2 h1 = __floats2half2_rn(oz * ns, ow * ns);
        uint2 o;
        o.x = *(unsigned*)&h0;
        o.y = *(unsigned*)&h1;
        ((uint2*)g_h1s)[n * 32 + lane] = o;
    } else {
        float4 wd = ((const float4*)Wd)[lane];
        float z = ox * wd.x + oy * wd.y + oz * wd.z + ow * wd.w;
        #pragma unroll
        for (int off = 16; off > 0; off >>= 1)
            z += __shfl_xor_sync(0xffffffffu, z, off);
        if (lane == 0) atomicAdd(&g_gsum[gids[n]], z);
    }
}

// ---------------- [7] readout + re-zero degree arrays for next run ----------------
__global__ void k_final(const float* __restrict__ bd, float* __restrict__ out) {
    int i = blockIdx.x * blockDim.x + threadIdx.x;
    if (i < N_NODES) { g_deg_out[i] = 0; g_deg_in[i] = 0; }
    if (i < N_GRAPHS) out[i] = g_gsum[i] * g_ginv[i] + bd[0];
}

// ---------------- launch ----------------
extern "C" void kernel_launch(void* const* d_in, const int* in_sizes, int n_in,
                              void* d_out, int out_size) {
    const float* in_feat = (const float*)d_in[0];
    const int*   src     = (const int*)  d_in[1];
    const int*   dst     = (const int*)  d_in[2];
    const int*   gids    = (const int*)  d_in[3];
    const float* W1      = (const float*)d_in[4];
    const float* b1      = (const float*)d_in[5];
    const float* W2      = (const float*)d_in[6];
    const float* b2      = (const float*)d_in[7];
    const float* Wd      = (const float*)d_in[8];
    const float* bd      = (const float*)d_in[9];
    float* out = (float*)d_out;

    int gemmBlocks  = N_NODES / 16;                    // 625 (10000 = 625*16 exact)
    int aggBlocks   = (N_NODES + 7) / 8;               // 1250
    int finalBlocks = (N_NODES + TB - 1) / TB;
    int ssBlocks    = EDGE4_BLOCKS + XS_BLOCKS + 2 * W_BLOCKS;

    k_degree        <<<EDGE4_BLOCKS, TB>>>(src, dst);                 // 0
    k_prep          <<<1, 1024>>>(gids);                              // 1
    k_scatter_scale <<<ssBlocks, TB>>>(src, dst, in_feat, W1, W2);    // 2
    k_gemm<1>       <<<gemmBlocks, TB>>>();                           // 3  (ncu slot)
    k_agg<1>        <<<aggBlocks, TB>>>(b1, nullptr, nullptr);        // 4
    k_gemm<2>       <<<gemmBlocks, TB>>>();                           // 5
    k_agg<2>        <<<aggBlocks, TB>>>(b2, Wd, gids);                // 6
    k_final         <<<finalBlocks, TB>>>(bd, out);                   // 7
}

// round 13
// speedup vs baseline: 1.0590x; 1.0153x over previous
#include <cuda_runtime.h>
#include <cuda_fp16.h>
#include <mma.h>

using namespace nvcuda;

#define N_NODES  10000
#define N_EDGES  640000
#define N_GRAPHS 64
#define F        128
#define PAD_ROWS 16                           // gemm tile overrun padding

// -------- device symbols: ONLY dereferenced inside kernels, never passed as args --------
__device__ int    g_deg_out[N_NODES];          // zeroed at load + by k_final each run
__device__ int    g_deg_in [N_NODES];
__device__ int    g_row_ptr[N_NODES + 1];
__device__ int    g_cursor [N_NODES];
__device__ int    g_csr    [N_EDGES];
__device__ __half g_xh     [(N_NODES + PAD_ROWS) * F];  // in_feat * norm_src      (fp16)
__device__ __half g_h1s    [(N_NODES + PAD_ROWS) * F];  // relu(layer1) * norm_src (fp16)
__device__ __half g_zh     [(N_NODES + PAD_ROWS) * F];  // Z = input @ W           (fp16)
__device__ __half g_w1h    [F * F];            // W1 fp16
__device__ __half g_w2h    [F * F];            // W2 fp16
__device__ float  g_gsum   [N_GRAPHS];
__device__ float  g_ginv   [N_GRAPHS];

#define TB 256

// ---------------- [0] degrees (4 edges per thread, int4 loads) ----------------
__global__ void k_degree(const int* __restrict__ src, const int* __restrict__ dst) {
    int i = blockIdx.x * blockDim.x + threadIdx.x;
    if (i < N_EDGES / 4) {
        int4 s = ((const int4*)src)[i];
        int4 d = ((const int4*)dst)[i];
        atomicAdd(&g_deg_out[s.x], 1);
        atomicAdd(&g_deg_out[s.y], 1);
        atomicAdd(&g_deg_out[s.z], 1);
        atomicAdd(&g_deg_out[s.w], 1);
        atomicAdd(&g_deg_in[d.x], 1);
        atomicAdd(&g_deg_in[d.y], 1);
        atomicAdd(&g_deg_in[d.z], 1);
        atomicAdd(&g_deg_in[d.w], 1);
    }
}

// ------ [1] prep: shuffle-scan of in-degrees + cursors + per-graph counts (binary search) ---
__global__ void k_prep(const int* __restrict__ gids) {
    const int T = 1024, C = 10;                // 1024*10 = 10240 >= N_NODES
    __shared__ int wsum[32];
    int t    = threadIdx.x;
    int wid  = t >> 5;
    int lane = t & 31;

    int base = t * C;
    int local = 0;
    #pragma unroll
    for (int i = 0; i < C; i++) {
        int idx = base + i;
        if (idx < N_NODES) local += g_deg_in[idx];
    }
    int v = local;
    #pragma unroll
    for (int off = 1; off < 32; off <<= 1) {
        int u = __shfl_up_sync(0xffffffffu, v, off);
        if (lane >= off) v += u;
    }
    if (lane == 31) wsum[wid] = v;
    __syncthreads();
    if (wid == 0) {
        int u = wsum[lane];
        #pragma unroll
        for (int off = 1; off < 32; off <<= 1) {
            int p = __shfl_up_sync(0xffffffffu, u, off);
            if (lane >= off) u += p;
        }
        wsum[lane] = u;
    }
    __syncthreads();
    int run = v - local + (wid > 0 ? wsum[wid - 1] : 0);
    #pragma unroll
    for (int i = 0; i < C; i++) {
        int idx = base + i;
        if (idx < N_NODES) {
            g_row_ptr[idx] = run;
            g_cursor [idx] = run;
            run += g_deg_in[idx];
        }
    }
    if (t == T - 1) g_row_ptr[N_NODES] = run;

    // per-graph counts: graph_ids is sorted -> binary search boundaries
    if (t < N_GRAPHS) {
        int lo = 0, hi = N_NODES;
        while (lo < hi) { int m = (lo + hi) >> 1; if (gids[m] < t) lo = m + 1; else hi = m; }
        int b0 = lo;
        lo = b0; hi = N_NODES;
        while (lo < hi) { int m = (lo + hi) >> 1; if (gids[m] < t + 1) lo = m + 1; else hi = m; }
        int c = lo - b0;
        g_gsum[t] = 0.f;
        g_ginv[t] = 1.f / fmaxf((float)c, 1.f);
    }
}

// ------- [2] scatter edges into CSR (int4) + prescale X to fp16 + convert W to fp16 -------
#define EDGE4_BLOCKS ((N_EDGES / 4 + TB - 1) / TB)
#define XS_BLOCKS    ((N_NODES * (F / 4) + TB - 1) / TB)
#define W_BLOCKS     ((F * F / 4 + TB - 1) / TB)

__global__ void k_scatter_scale(const int* __restrict__ src,
                                const int* __restrict__ dst,
                                const float* __restrict__ X,
                                const float* __restrict__ W1,
                                const float* __restrict__ W2) {
    int b = blockIdx.x;
    if (b < EDGE4_BLOCKS) {
        int i = b * TB + threadIdx.x;
        if (i < N_EDGES / 4) {
            int4 s = ((const int4*)src)[i];
            int4 d = ((const int4*)dst)[i];
            g_csr[atomicAdd(&g_cursor[d.x], 1)] = s.x;
            g_csr[atomicAdd(&g_cursor[d.y], 1)] = s.y;
            g_csr[atomicAdd(&g_cursor[d.z], 1)] = s.z;
            g_csr[atomicAdd(&g_cursor[d.w], 1)] = s.w;
        }
    } else if (b < EDGE4_BLOCKS + XS_BLOCKS) {
        int idx = (b - EDGE4_BLOCKS) * TB + threadIdx.x;
        if (idx < N_NODES * (F / 4)) {
            float s = rsqrtf((float)max(g_deg_out[idx >> 5], 1));   // norm_src inline
            float4 v = ((const float4*)X)[idx];
            __half2 h0 = __floats2half2_rn(v.x * s, v.y * s);
            __half2 h1 = __floats2half2_rn(v.z * s, v.w * s);
            uint2 o;
            o.x = *(unsigned*)&h0;
            o.y = *(unsigned*)&h1;
            ((uint2*)g_xh)[idx] = o;
        }
    } else {
        int idx = (b - EDGE4_BLOCKS - XS_BLOCKS) * TB + threadIdx.x;
        if (idx < 2 * (F * F / 4)) {
            int m = idx >= F * F / 4;
            int i = m ? idx - F * F / 4 : idx;
            float4 v = ((const float4*)(m ? W2 : W1))[i];
            __half2 h0 = __floats2half2_rn(v.x, v.y);
            __half2 h1 = __floats2half2_rn(v.z, v.w);
            uint2 o;
            o.x = *(unsigned*)&h0;
            o.y = *(unsigned*)&h1;
            ((uint2*)(m ? g_w2h : g_w1h))[i] = o;
        }
    }
}

// -------- [3]/[5] dense GEMM via wmma, smem-staged: Z = A @ W  (fp16, 32 rows/block) -------
// 8 warps; warp w owns col tile w*16 and both row tiles. W + A-tile staged in smem.
template <int LAYER>    // 1: A=g_xh, W=g_w1h; 2: A=g_h1s, W=g_w2h
__global__ __launch_bounds__(256) void k_gemm() {
    __shared__ __half sW[F * F];        // 32 KB
    __shared__ __half sA[32 * F];       // 8 KB
    const __half* A  = LAYER == 1 ? g_xh  : g_h1s;
    const __half* Wg = LAYER == 1 ? g_w1h : g_w2h;
    int tid  = threadIdx.x;
    int warp = tid >> 5;
    int row0 = blockIdx.x * 32;

    // stage W: 16384 halves = 2048 uint4 ; A tile: 4096 halves = 512 uint4
    {
        const uint4* Wg4 = (const uint4*)Wg;
        uint4* sW4 = (uint4*)sW;
        #pragma unroll
        for (int i = 0; i < 8; i++) sW4[i * 256 + tid] = Wg4[i * 256 + tid];
        const uint4* Ag4 = (const uint4*)(A + (size_t)row0 * F);
        uint4* sA4 = (uint4*)sA;
        #pragma unroll
        for (int i = 0; i < 2; i++) sA4[i * 256 + tid] = Ag4[i * 256 + tid];
    }
    __syncthreads();

    int col0 = warp * 16;
    wmma::fragment<wmma::matrix_a, 16, 16, 16, half, wmma::row_major> af;
    wmma::fragment<wmma::matrix_b, 16, 16, 16, half, wmma::row_major> bf;

    #pragma unroll
    for (int rt = 0; rt < 2; rt++) {
        wmma::fragment<wmma::accumulator, 16, 16, 16, half> cf;
        wmma::fill_fragment(cf, __float2half(0.f));
        #pragma unroll
        for (int k = 0; k < F / 16; k++) {
            wmma::load_matrix_sync(af, (const half*)sA + (rt * 16) * F + k * 16, F);
            wmma::load_matrix_sync(bf, (const half*)sW + (k * 16) * F + col0, F);
            wmma::mma_sync(cf, af, bf, cf);
        }
        wmma::store_matrix_sync((half*)g_zh + (size_t)(row0 + rt * 16) * F + col0,
                                cf, F, wmma::mem_row_major);
    }
}

// ---------------- [4]/[6] aggregate: warp-per-node gather of Z + epilogue ----------------
template <int LAYER>    // 1: write h1s = relu(nd*acc+b)*ns; 2: pool relu(nd*acc+b).Wd
__global__ __launch_bounds__(256) void k_agg(const float* __restrict__ b,
                                             const float* __restrict__ Wd,
                                             const int*  __restrict__ gids) {
    const int WARPS = 8;
    int w    = threadIdx.x >> 5;
    int lane = threadIdx.x & 31;
    int n    = blockIdx.x * WARPS + w;
    if (n >= N_NODES) return;

    const uint2* Z = (const uint2*)g_zh;

    int beg = g_row_ptr[n], end = g_row_ptr[n + 1];
    float ax = 0.f, ay = 0.f, az = 0.f, aw = 0.f;
    int e = beg;
    #define ACC(v) { \
        float2 f0 = __half22float2(*(__half2*)&(v).x); \
        float2 f1 = __half22float2(*(__half2*)&(v).y); \
        ax += f0.x; ay += f0.y; az += f1.x; aw += f1.y; }
    for (; e + 16 <= end; e += 16) {               // 32 loads in flight
        uint2 v[16];
        #pragma unroll
        for (int q = 0; q < 16; q++) v[q] = Z[g_csr[e + q] * 32 + lane];
        #pragma unroll
        for (int q = 0; q < 16; q++) ACC(v[q])
    }
    for (; e + 4 <= end; e += 4) {
        uint2 v0 = Z[g_csr[e+0] * 32 + lane];
        uint2 v1 = Z[g_csr[e+1] * 32 + lane];
        uint2 v2 = Z[g_csr[e+2] * 32 + lane];
        uint2 v3 = Z[g_csr[e+3] * 32 + lane];
        ACC(v0) ACC(v1) ACC(v2) ACC(v3)
    }
    for (; e < end; e++) {
        uint2 v = Z[g_csr[e] * 32 + lane];
        ACC(v)
    }
    #undef ACC

    float nd = rsqrtf((float)max(g_deg_in[n], 1));   // norm_dst inline
    float4 bv = ((const float4*)b)[lane];
    float ox = fmaxf(ax * nd + bv.x, 0.f);
    float oy = fmaxf(ay * nd + bv.y, 0.f);
    float oz = fmaxf(az * nd + bv.z, 0.f);
    float ow = fmaxf(aw * nd + bv.w, 0.f);

    if (LAYER == 1) {
        float ns = rsqrtf((float)max(g_deg_out[n], 1));  // prescale for layer-2 GEMM
        __half2 h0 = __floats2half2_rn(ox * ns, oy * ns);
        __half2 h1 = __floats2half2_rn(oz * ns, ow * ns);
        uint2 o;
        o.x = *(unsigned*)&h0;
        o.y = *(unsigned*)&h1;
        ((uint2*)g_h1s)[n * 32 + lane] = o;
    } else {
        float4 wd = ((const float4*)Wd)[lane];
        float z = ox * wd.x + oy * wd.y + oz * wd.z + ow * wd.w;
        #pragma unroll
        for (int off = 16; off > 0; off >>= 1)
            z += __shfl_xor_sync(0xffffffffu, z, off);
        if (lane == 0) atomicAdd(&g_gsum[gids[n]], z);
    }
}

// ---------------- [7] readout + re-zero degree arrays for next run ----------------
__global__ void k_final(const float* __restrict__ bd, float* __restrict__ out) {
    int i = blockIdx.x * blockDim.x + threadIdx.x;
    if (i < N_NODES) { g_deg_out[i] = 0; g_deg_in[i] = 0; }
    if (i < N_GRAPHS) out[i] = g_gsum[i] * g_ginv[i] + bd[0];
}

// ---------------- launch ----------------
extern "C" void kernel_launch(void* const* d_in, const int* in_sizes, int n_in,
                              void* d_out, int out_size) {
    const float* in_feat = (const float*)d_in[0];
    const int*   src     = (const int*)  d_in[1];
    const int*   dst     = (const int*)  d_in[2];
    const int*   gids    = (const int*)  d_in[3];
    const float* W1      = (const float*)d_in[4];
    const float* b1      = (const float*)d_in[5];
    const float* W2      = (const float*)d_in[6];
    const float* b2      = (const float*)d_in[7];
    const float* Wd      = (const float*)d_in[8];
    const float* bd      = (const float*)d_in[9];
    float* out = (float*)d_out;

    int gemmBlocks  = (N_NODES + 31) / 32;             // 313 (padded arrays absorb overrun)
    int aggBlocks   = (N_NODES + 7) / 8;               // 1250
    int finalBlocks = (N_NODES + TB - 1) / TB;
    int ssBlocks    = EDGE4_BLOCKS + XS_BLOCKS + 2 * W_BLOCKS;

    k_degree        <<<EDGE4_BLOCKS, TB>>>(src, dst);                 // 0
    k_prep          <<<1, 1024>>>(gids);                              // 1
    k_scatter_scale <<<ssBlocks, TB>>>(src, dst, in_feat, W1, W2);    // 2
    k_gemm<1>       <<<gemmBlocks, TB>>>();                           // 3  (ncu slot)
    k_agg<1>        <<<aggBlocks, TB>>>(b1, nullptr, nullptr);        // 4
    k_gemm<2>       <<<gemmBlocks, TB>>>();                           // 5
    k_agg<2>        <<<aggBlocks, TB>>>(b2, Wd, gids);                // 6
    k_final         <<<finalBlocks, TB>>>(bd, out);                   // 7
}

// round 14
// speedup vs baseline: 1.2462x; 1.1768x over previous
#include <cuda_runtime.h>
#include <cuda_fp16.h>
#include <mma.h>

using namespace nvcuda;

#define N_NODES  10000
#define N_EDGES  640000
#define N_GRAPHS 64
#define F        128
#define PAD_ROWS 16                           // gemm tile overrun padding
#define LDS_PAD  136                          // smem row stride in halves (272B, conflict-free)

// -------- device symbols: ONLY dereferenced inside kernels, never passed as args --------
__device__ int    g_deg_out[N_NODES];          // zeroed at load + by k_final each run
__device__ int    g_deg_in [N_NODES];
__device__ int    g_row_ptr[N_NODES + 1];
__device__ int    g_cursor [N_NODES];
__device__ int    g_csr    [N_EDGES];
__device__ __half g_xh     [(N_NODES + PAD_ROWS) * F];  // in_feat * norm_src      (fp16)
__device__ __half g_h1s    [(N_NODES + PAD_ROWS) * F];  // relu(layer1) * norm_src (fp16)
__device__ __half g_zh     [(N_NODES + PAD_ROWS) * F];  // Z = input @ W           (fp16)
__device__ __half g_w1h    [F * F];            // W1 fp16
__device__ __half g_w2h    [F * F];            // W2 fp16
__device__ float  g_gsum   [N_GRAPHS];
__device__ float  g_ginv   [N_GRAPHS];

#define TB 256

// ---------------- [0] degrees (4 edges per thread, int4 loads) ----------------
__global__ void k_degree(const int* __restrict__ src, const int* __restrict__ dst) {
    int i = blockIdx.x * blockDim.x + threadIdx.x;
    if (i < N_EDGES / 4) {
        int4 s = ((const int4*)src)[i];
        int4 d = ((const int4*)dst)[i];
        atomicAdd(&g_deg_out[s.x], 1);
        atomicAdd(&g_deg_out[s.y], 1);
        atomicAdd(&g_deg_out[s.z], 1);
        atomicAdd(&g_deg_out[s.w], 1);
        atomicAdd(&g_deg_in[d.x], 1);
        atomicAdd(&g_deg_in[d.y], 1);
        atomicAdd(&g_deg_in[d.z], 1);
        atomicAdd(&g_deg_in[d.w], 1);
    }
}

// ------ [1] prep: shuffle-scan of in-degrees + cursors + per-graph counts (binary search) ---
__global__ void k_prep(const int* __restrict__ gids) {
    const int T = 1024, C = 10;                // 1024*10 = 10240 >= N_NODES
    __shared__ int wsum[32];
    int t    = threadIdx.x;
    int wid  = t >> 5;
    int lane = t & 31;

    int base = t * C;
    int local = 0;
    #pragma unroll
    for (int i = 0; i < C; i++) {
        int idx = base + i;
        if (idx < N_NODES) local += g_deg_in[idx];
    }
    int v = local;
    #pragma unroll
    for (int off = 1; off < 32; off <<= 1) {
        int u = __shfl_up_sync(0xffffffffu, v, off);
        if (lane >= off) v += u;
    }
    if (lane == 31) wsum[wid] = v;
    __syncthreads();
    if (wid == 0) {
        int u = wsum[lane];
        #pragma unroll
        for (int off = 1; off < 32; off <<= 1) {
            int p = __shfl_up_sync(0xffffffffu, u, off);
            if (lane >= off) u += p;
        }
        wsum[lane] = u;
    }
    __syncthreads();
    int run = v - local + (wid > 0 ? wsum[wid - 1] : 0);
    #pragma unroll
    for (int i = 0; i < C; i++) {
        int idx = base + i;
        if (idx < N_NODES) {
            g_row_ptr[idx] = run;
            g_cursor [idx] = run;
            run += g_deg_in[idx];
        }
    }
    if (t == T - 1) g_row_ptr[N_NODES] = run;

    // per-graph counts: graph_ids is sorted -> binary search boundaries
    if (t < N_GRAPHS) {
        int lo = 0, hi = N_NODES;
        while (lo < hi) { int m = (lo + hi) >> 1; if (gids[m] < t) lo = m + 1; else hi = m; }
        int b0 = lo;
        lo = b0; hi = N_NODES;
        while (lo < hi) { int m = (lo + hi) >> 1; if (gids[m] < t + 1) lo = m + 1; else hi = m; }
        int c = lo - b0;
        g_gsum[t] = 0.f;
        g_ginv[t] = 1.f / fmaxf((float)c, 1.f);
    }
}

// ------- [2] scatter edges into CSR (int4) + prescale X to fp16 + convert W to fp16 -------
#define EDGE4_BLOCKS ((N_EDGES / 4 + TB - 1) / TB)
#define XS_BLOCKS    ((N_NODES * (F / 4) + TB - 1) / TB)
#define W_BLOCKS     ((F * F / 4 + TB - 1) / TB)

__global__ void k_scatter_scale(const int* __restrict__ src,
                                const int* __restrict__ dst,
                                const float* __restrict__ X,
                                const float* __restrict__ W1,
                                const float* __restrict__ W2) {
    int b = blockIdx.x;
    if (b < EDGE4_BLOCKS) {
        int i = b * TB + threadIdx.x;
        if (i < N_EDGES / 4) {
            int4 s = ((const int4*)src)[i];
            int4 d = ((const int4*)dst)[i];
            g_csr[atomicAdd(&g_cursor[d.x], 1)] = s.x;
            g_csr[atomicAdd(&g_cursor[d.y], 1)] = s.y;
            g_csr[atomicAdd(&g_cursor[d.z], 1)] = s.z;
            g_csr[atomicAdd(&g_cursor[d.w], 1)] = s.w;
        }
    } else if (b < EDGE4_BLOCKS + XS_BLOCKS) {
        int idx = (b - EDGE4_BLOCKS) * TB + threadIdx.x;
        if (idx < N_NODES * (F / 4)) {
            float s = rsqrtf((float)max(g_deg_out[idx >> 5], 1));   // norm_src inline
            float4 v = ((const float4*)X)[idx];
            __half2 h0 = __floats2half2_rn(v.x * s, v.y * s);
            __half2 h1 = __floats2half2_rn(v.z * s, v.w * s);
            uint2 o;
            o.x = *(unsigned*)&h0;
            o.y = *(unsigned*)&h1;
            ((uint2*)g_xh)[idx] = o;
        }
    } else {
        int idx = (b - EDGE4_BLOCKS - XS_BLOCKS) * TB + threadIdx.x;
        if (idx < 2 * (F * F / 4)) {
            int m = idx >= F * F / 4;
            int i = m ? idx - F * F / 4 : idx;
            float4 v = ((const float4*)(m ? W2 : W1))[i];
            __half2 h0 = __floats2half2_rn(v.x, v.y);
            __half2 h1 = __floats2half2_rn(v.z, v.w);
            uint2 o;
            o.x = *(unsigned*)&h0;
            o.y = *(unsigned*)&h1;
            ((uint2*)(m ? g_w2h : g_w1h))[i] = o;
        }
    }
}

// -------- [3]/[5] dense GEMM via wmma, padded smem tiles (conflict-free fragment loads) ----
// 8 warps; warp w owns col tile w*16 and both row tiles of a 32-row block.
template <int LAYER>    // 1: A=g_xh, W=g_w1h; 2: A=g_h1s, W=g_w2h
__global__ __launch_bounds__(256) void k_gemm() {
    __shared__ __half sW[F * LDS_PAD];        // 128 x 136 = 34 KB
    __shared__ __half sA[32 * LDS_PAD];       //  32 x 136 = 8.7 KB
    const __half* A  = LAYER == 1 ? g_xh  : g_h1s;
    const __half* Wg = LAYER == 1 ? g_w1h : g_w2h;
    int tid  = threadIdx.x;
    int warp = tid >> 5;
    int row0 = blockIdx.x * 32;

    // stage W (2048 uint4) and A tile (512 uint4) into padded smem rows
    {
        const uint4* Wg4 = (const uint4*)Wg;
        #pragma unroll
        for (int i = 0; i < 8; i++) {
            int idx = i * 256 + tid;           // uint4 index in the dense source
            int row = idx >> 4;                // 16 uint4 per row
            int col = (idx & 15) * 8;          // half offset within row
            *(uint4*)(sW + row * LDS_PAD + col) = Wg4[idx];
        }
        const uint4* Ag4 = (const uint4*)(A + (size_t)row0 * F);
        #pragma unroll
        for (int i = 0; i < 2; i++) {
            int idx = i * 256 + tid;
            int row = idx >> 4;
            int col = (idx & 15) * 8;
            *(uint4*)(sA + row * LDS_PAD + col) = Ag4[idx];
        }
    }
    __syncthreads();

    int col0 = warp * 16;
    wmma::fragment<wmma::matrix_a, 16, 16, 16, half, wmma::row_major> af;
    wmma::fragment<wmma::matrix_b, 16, 16, 16, half, wmma::row_major> bf;

    #pragma unroll
    for (int rt = 0; rt < 2; rt++) {
        wmma::fragment<wmma::accumulator, 16, 16, 16, half> cf;
        wmma::fill_fragment(cf, __float2half(0.f));
        #pragma unroll
        for (int k = 0; k < F / 16; k++) {
            wmma::load_matrix_sync(af, (const half*)sA + (rt * 16) * LDS_PAD + k * 16, LDS_PAD);
            wmma::load_matrix_sync(bf, (const half*)sW + (k * 16) * LDS_PAD + col0, LDS_PAD);
            wmma::mma_sync(cf, af, bf, cf);
        }
        wmma::store_matrix_sync((half*)g_zh + (size_t)(row0 + rt * 16) * F + col0,
                                cf, F, wmma::mem_row_major);
    }
}

// ---------------- [4]/[6] aggregate: warp-per-node gather of Z + epilogue ----------------
template <int LAYER>    // 1: write h1s = relu(nd*acc+b)*ns; 2: pool relu(nd*acc+b).Wd
__global__ __launch_bounds__(256) void k_agg(const float* __restrict__ b,
                                             const float* __restrict__ Wd,
                                             const int*  __restrict__ gids) {
    const int WARPS = 8;
    int w    = threadIdx.x >> 5;
    int lane = threadIdx.x & 31;
    int n    = blockIdx.x * WARPS + w;
    if (n >= N_NODES) return;

    const uint2* Z = (const uint2*)g_zh;

    int beg = g_row_ptr[n], end = g_row_ptr[n + 1];
    float ax = 0.f, ay = 0.f, az = 0.f, aw = 0.f;
    int e = beg;
    #define ACC(v) { \
        float2 f0 = __half22float2(*(__half2*)&(v).x); \
        float2 f1 = __half22float2(*(__half2*)&(v).y); \
        ax += f0.x; ay += f0.y; az += f1.x; aw += f1.y; }
    for (; e + 16 <= end; e += 16) {               // 32 loads in flight
        uint2 v[16];
        #pragma unroll
        for (int q = 0; q < 16; q++) v[q] = Z[g_csr[e + q] * 32 + lane];
        #pragma unroll
        for (int q = 0; q < 16; q++) ACC(v[q])
    }
    for (; e + 4 <= end; e += 4) {
        uint2 v0 = Z[g_csr[e+0] * 32 + lane];
        uint2 v1 = Z[g_csr[e+1] * 32 + lane];
        uint2 v2 = Z[g_csr[e+2] * 32 + lane];
        uint2 v3 = Z[g_csr[e+3] * 32 + lane];
        ACC(v0) ACC(v1) ACC(v2) ACC(v3)
    }
    for (; e < end; e++) {
        uint2 v = Z[g_csr[e] * 32 + lane];
        ACC(v)
    }
    #undef ACC

    float nd = rsqrtf((float)max(g_deg_in[n], 1));   // norm_dst inline
    float4 bv = ((const float4*)b)[lane];
    float ox = fmaxf(ax * nd + bv.x, 0.f);
    float oy = fmaxf(ay * nd + bv.y, 0.f);
    float oz = fmaxf(az * nd + bv.z, 0.f);
    float ow = fmaxf(aw * nd + bv.w, 0.f);

    if (LAYER == 1) {
        float ns = rsqrtf((float)max(g_deg_out[n], 1));  // prescale for layer-2 GEMM
        __half2 h0 = __floats2half2_rn(ox * ns, oy * ns);
        __half2 h1 = __floats2half2_rn(oz * ns, ow * ns);
        uint2 o;
        o.x = *(unsigned*)&h0;
        o.y = *(unsigned*)&h1;
        ((uint2*)g_h1s)[n * 32 + lane] = o;
    } else {
        float4 wd = ((const float4*)Wd)[lane];
        float z = ox * wd.x + oy * wd.y + oz * wd.z + ow * wd.w;
        #pragma unroll
        for (int off = 16; off > 0; off >>= 1)
            z += __shfl_xor_sync(0xffffffffu, z, off);
        if (lane == 0) atomicAdd(&g_gsum[gids[n]], z);
    }
}

// ---------------- [7] readout + re-zero degree arrays for next run ----------------
__global__ void k_final(const float* __restrict__ bd, float* __restrict__ out) {
    int i = blockIdx.x * blockDim.x + threadIdx.x;
    if (i < N_NODES) { g_deg_out[i] = 0; g_deg_in[i] = 0; }
    if (i < N_GRAPHS) out[i] = g_gsum[i] * g_ginv[i] + bd[0];
}

// ---------------- launch ----------------
extern "C" void kernel_launch(void* const* d_in, const int* in_sizes, int n_in,
                              void* d_out, int out_size) {
    const float* in_feat = (const float*)d_in[0];
    const int*   src     = (const int*)  d_in[1];
    const int*   dst     = (const int*)  d_in[2];
    const int*   gids    = (const int*)  d_in[3];
    const float* W1      = (const float*)d_in[4];
    const float* b1      = (const float*)d_in[5];
    const float* W2      = (const float*)d_in[6];
    const float* b2      = (const float*)d_in[7];
    const float* Wd      = (const float*)d_in[8];
    const float* bd      = (const float*)d_in[9];
    float* out = (float*)d_out;

    int gemmBlocks  = (N_NODES + 31) / 32;             // 313 (padded arrays absorb overrun)
    int aggBlocks   = (N_NODES + 7) / 8;               // 1250
    int finalBlocks = (N_NODES + TB - 1) / TB;
    int ssBlocks    = EDGE4_BLOCKS + XS_BLOCKS + 2 * W_BLOCKS;

    k_degree        <<<EDGE4_BLOCKS, TB>>>(src, dst);                 // 0
    k_prep          <<<1, 1024>>>(gids);                              // 1
    k_scatter_scale <<<ssBlocks, TB>>>(src, dst, in_feat, W1, W2);    // 2
    k_gemm<1>       <<<gemmBlocks, TB>>>();                           // 3  (ncu slot)
    k_agg<1>        <<<aggBlocks, TB>>>(b1, nullptr, nullptr);        // 4
    k_gemm<2>       <<<gemmBlocks, TB>>>();                           // 5
    k_agg<2>        <<<aggBlocks, TB>>>(b2, Wd, gids);                // 6
    k_final         <<<finalBlocks, TB>>>(bd, out);                   // 7
}